// round 1
// baseline (speedup 1.0000x reference)
#include <cuda_runtime.h>

// Zero the scalar output (d_out is poisoned to 0xAA by the harness).
__global__ void init_out_kernel(float* out) {
    out[0] = 0.0f;
}

// Grid-stride sum of squared differences over float4-vectorized data.
// Each block does a warp-shuffle + shared-memory reduction, then one
// atomicAdd of (block_sum * scale) into the scalar output.
__global__ void sse_reduce_kernel(const float4* __restrict__ p,
                                  const float4* __restrict__ t,
                                  float* __restrict__ out,
                                  int n4, float scale) {
    float acc = 0.0f;
    int idx = blockIdx.x * blockDim.x + threadIdx.x;
    int stride = gridDim.x * blockDim.x;

    // Main grid-stride loop over float4 elements (16B per load, 2 streams).
    for (int i = idx; i < n4; i += stride) {
        float4 a = __ldg(&p[i]);
        float4 b = __ldg(&t[i]);
        float d0 = a.x - b.x;
        float d1 = a.y - b.y;
        float d2 = a.z - b.z;
        float d3 = a.w - b.w;
        acc = fmaf(d0, d0, acc);
        acc = fmaf(d1, d1, acc);
        acc = fmaf(d2, d2, acc);
        acc = fmaf(d3, d3, acc);
    }

    // Warp reduction
    #pragma unroll
    for (int off = 16; off > 0; off >>= 1)
        acc += __shfl_down_sync(0xFFFFFFFFu, acc, off);

    // Block reduction via shared memory
    __shared__ float warp_sums[8];  // 256 threads = 8 warps
    int lane = threadIdx.x & 31;
    int wid  = threadIdx.x >> 5;
    if (lane == 0) warp_sums[wid] = acc;
    __syncthreads();

    if (wid == 0) {
        float v = (lane < (blockDim.x >> 5)) ? warp_sums[lane] : 0.0f;
        #pragma unroll
        for (int off = 4; off > 0; off >>= 1)
            v += __shfl_down_sync(0xFFFFFFFFu, v, off);
        if (lane == 0)
            atomicAdd(out, v * scale);
    }
}

extern "C" void kernel_launch(void* const* d_in, const int* in_sizes, int n_in,
                              void* d_out, int out_size) {
    const float* pred = (const float*)d_in[0];
    const float* targ = (const float*)d_in[1];
    float* out = (float*)d_out;

    int n = in_sizes[0];       // B * S * 2 = 16,769,024 (divisible by 4)
    int n4 = n / 4;
    // total / S / batch = total * 2 / n
    float scale = 2.0f / (float)n;

    init_out_kernel<<<1, 1>>>(out);

    const int threads = 256;
    const int blocks = 1184;   // 8 CTAs per SM on 148 SMs
    sse_reduce_kernel<<<blocks, threads>>>((const float4*)pred,
                                           (const float4*)targ,
                                           out, n4, scale);
}